// round 5
// baseline (speedup 1.0000x reference)
#include <cuda_runtime.h>
#include <cuda_bf16.h>
#include <cstdint>

// Problem constants
#define C_IN    256
#define S_SEQ   90
#define K_DIM   180
#define B_BATCH 4096
#define N_OUT   2086
#define MT      (B_BATCH / 128)        // 32 m-tile images
#define NT      ((N_OUT + 127) / 128)  // 17 n-tiles
#define PITCH   200                    // row pitch in bf16 elems (400B -> conflict-free ldmatrix)
#define TILE_E  (128 * PITCH)          // elems per 128-row tile image

// Tile images: [row][k] bf16, pitch 200. k in [180,200) stays ZERO (zero-init,
// never written) because the GEMM consumes k in [0,192).
__device__ __align__(16) __nv_bfloat16 g_Ahi[MT * TILE_E];
__device__ __align__(16) __nv_bfloat16 g_Alo[MT * TILE_E];
__device__ __align__(16) __nv_bfloat16 g_Bhi[NT * TILE_E];
__device__ __align__(16) __nv_bfloat16 g_Blo[NT * TILE_E];

__device__ __forceinline__ void store_split(__nv_bfloat16* hi_arr,
                                            __nv_bfloat16* lo_arr,
                                            size_t idx, float v) {
    __nv_bfloat16 hi = __float2bfloat16(v);
    hi_arr[idx] = hi;
    lo_arr[idx] = __float2bfloat16(v - __bfloat162float(hi));
}

// ---------------------------------------------------------------------------
// Kernel: fc_w [2086,180] -> bf16 hi/lo tile images
// ---------------------------------------------------------------------------
__global__ void prep_b_kernel(const float* __restrict__ fc_w) {
    int i = blockIdx.x * 256 + threadIdx.x;
    if (i >= N_OUT * K_DIM) return;
    int n = i / K_DIM;
    int k = i - n * K_DIM;
    size_t idx = (size_t)(n >> 7) * TILE_E + (n & 127) * PITCH + k;
    store_split(g_Bhi, g_Blo, idx, fc_w[i]);
}

// ---------------------------------------------------------------------------
// Kernel: conv1x1 + BN + attention(head_dim=1) + out_proj -> bf16 hi/lo A tiles
// 768 threads: thread (cc, s) accumulates 32 channels; 8-way smem reduction.
// ---------------------------------------------------------------------------
__global__ __launch_bounds__(768) void head_kernel(
    const float* __restrict__ x,
    const float* __restrict__ conv_w,
    const float* __restrict__ bn_gamma, const float* __restrict__ bn_beta,
    const float* __restrict__ bn_mean,  const float* __restrict__ bn_var,
    const float* __restrict__ in_proj_w, const float* __restrict__ in_proj_b,
    const float* __restrict__ out_proj_w, const float* __restrict__ out_proj_b)
{
    __shared__ float sw0[C_IN], sw1[C_IN];
    __shared__ float part0[8][96], part1[8][96];
    __shared__ float sk0[S_SEQ], sk1[S_SEQ], sv0[S_SEQ], sv1[S_SEQ];
    __shared__ float sred[4];

    const int b   = blockIdx.x;
    const int tid = threadIdx.x;
    const int cc  = tid / 96;       // channel chunk 0..7 (32 channels each)
    const int s   = tid - cc * 96;  // 0..95 (s<90 active)

    if (tid < C_IN) {
        sw0[tid] = conv_w[tid];
        sw1[tid] = conv_w[C_IN + tid];
    }
    __syncthreads();

    {
        float a0 = 0.f, a1 = 0.f;
        if (s < S_SEQ) {
            const float* xb = x + (size_t)b * (C_IN * S_SEQ) + cc * (32 * S_SEQ) + s;
            const float* w0 = sw0 + cc * 32;
            const float* w1 = sw1 + cc * 32;
#pragma unroll
            for (int c = 0; c < 32; ++c) {
                float xv = __ldg(xb + c * S_SEQ);
                a0 = fmaf(w0[c], xv, a0);
                a1 = fmaf(w1[c], xv, a1);
            }
        }
        part0[cc][s] = a0;
        part1[cc][s] = a1;
    }
    __syncthreads();

    float q0 = 0.f, q1 = 0.f;
    if (tid < S_SEQ) {
        float a0 = 0.f, a1 = 0.f;
#pragma unroll
        for (int j = 0; j < 8; ++j) {
            a0 += part0[j][tid];
            a1 += part1[j][tid];
        }
        float s0 = bn_gamma[0] * rsqrtf(bn_var[0] + 1e-5f);
        float s1 = bn_gamma[1] * rsqrtf(bn_var[1] + 1e-5f);
        float y0 = fmaf(a0, s0, bn_beta[0] - bn_mean[0] * s0);
        float y1 = fmaf(a1, s1, bn_beta[1] - bn_mean[1] * s1);
        q0       = fmaf(y0, in_proj_w[0],  fmaf(y1, in_proj_w[1],  in_proj_b[0]));
        q1       = fmaf(y0, in_proj_w[2],  fmaf(y1, in_proj_w[3],  in_proj_b[1]));
        sk0[tid] = fmaf(y0, in_proj_w[4],  fmaf(y1, in_proj_w[5],  in_proj_b[2]));
        sk1[tid] = fmaf(y0, in_proj_w[6],  fmaf(y1, in_proj_w[7],  in_proj_b[3]));
        sv0[tid] = fmaf(y0, in_proj_w[8],  fmaf(y1, in_proj_w[9],  in_proj_b[4]));
        sv1[tid] = fmaf(y0, in_proj_w[10], fmaf(y1, in_proj_w[11], in_proj_b[5]));
    }
    __syncthreads();

    // per-head k max/min for exact stable softmax
    if (tid < 64) {
        int h = tid >> 5, lane = tid & 31;
        const float* kk = h ? sk1 : sk0;
        float mx = -3.4e38f, mn = 3.4e38f;
        for (int j = lane; j < S_SEQ; j += 32) {
            float kv = kk[j];
            mx = fmaxf(mx, kv);
            mn = fminf(mn, kv);
        }
        for (int o = 16; o > 0; o >>= 1) {
            mx = fmaxf(mx, __shfl_xor_sync(0xffffffffu, mx, o));
            mn = fminf(mn, __shfl_xor_sync(0xffffffffu, mn, o));
        }
        if (lane == 0) { sred[h * 2] = mx; sred[h * 2 + 1] = mn; }
    }
    __syncthreads();

    if (tid < S_SEQ) {
        float m0 = fmaxf(q0 * sred[0], q0 * sred[1]);
        float m1 = fmaxf(q1 * sred[2], q1 * sred[3]);
        float d0 = 0.f, n0 = 0.f, d1 = 0.f, n1 = 0.f;
#pragma unroll 5
        for (int j = 0; j < S_SEQ; ++j) {
            float e0 = __expf(fmaf(q0, sk0[j], -m0));
            float e1 = __expf(fmaf(q1, sk1[j], -m1));
            d0 += e0; n0 = fmaf(e0, sv0[j], n0);
            d1 += e1; n1 = fmaf(e1, sv1[j], n1);
        }
        float o0 = n0 / d0, o1 = n1 / d1;
        float f0 = fmaf(o0, out_proj_w[0], fmaf(o1, out_proj_w[1], out_proj_b[0]));
        float f1 = fmaf(o0, out_proj_w[2], fmaf(o1, out_proj_w[3], out_proj_b[1]));
        size_t base = (size_t)(b >> 7) * TILE_E + (size_t)(b & 127) * PITCH;
        store_split(g_Ahi, g_Alo, base + tid,         f0);  // k = s
        store_split(g_Ahi, g_Alo, base + S_SEQ + tid, f1);  // k = 90 + s
    }
}

// ---------------------------------------------------------------------------
// FC GEMM: single-wave persistent tiles. Grid (17 nt, 8 mgroups) = 136 CTAs.
// Each CTA: B tile (hi+lo) resident; sweeps 8 m-subtiles of 64 rows with
// double-buffered cp.async A streaming. mma.sync m16n8k16 bf16 hi/lo split.
// 256 threads (8 warps), warp tile 32x32.
// ---------------------------------------------------------------------------
#define OFF_BHI 0
#define OFF_BLO 51200
#define OFF_A   102400     // + buf*51200 : hi at +0, lo at +25600
#define SMEM_TOTAL 204800

__device__ __forceinline__ uint32_t smem_u32(const void* p) {
    uint32_t a;
    asm("{ .reg .u64 t; cvta.to.shared.u64 t, %1; cvt.u32.u64 %0, t; }"
        : "=r"(a) : "l"(p));
    return a;
}

#define CP16(dst, src)                                                         \
    asm volatile("cp.async.cg.shared.global [%0], [%1], 16;"                   \
                 :: "r"(dst), "l"(src))

#define LDSM4(r, addr)                                                         \
    asm volatile("ldmatrix.sync.aligned.m8n8.x4.shared.b16 {%0,%1,%2,%3}, [%4];" \
                 : "=r"((r)[0]), "=r"((r)[1]), "=r"((r)[2]), "=r"((r)[3])      \
                 : "r"(addr))

#define MMA16816(c, a, b0v, b1v)                                               \
    asm volatile(                                                              \
        "mma.sync.aligned.m16n8k16.row.col.f32.bf16.bf16.f32 "                 \
        "{%0,%1,%2,%3}, {%4,%5,%6,%7}, {%8,%9}, {%0,%1,%2,%3};"                \
        : "+f"((c)[0]), "+f"((c)[1]), "+f"((c)[2]), "+f"((c)[3])               \
        : "r"((a)[0]), "r"((a)[1]), "r"((a)[2]), "r"((a)[3]),                  \
          "r"(b0v), "r"(b1v))

__global__ __launch_bounds__(256, 1) void fc_mma_kernel(
    const float* __restrict__ fc_b, float* __restrict__ out)
{
    extern __shared__ char sm[];
    const uint32_t sb = smem_u32(sm);
    const int tid = threadIdx.x;
    const int wid = tid >> 5;
    const int l   = tid & 31;
    const int nt = blockIdx.x;     // 0..16
    const int mg = blockIdx.y;     // 0..7
    const int n0 = nt * 128;

    // ---- stage B (resident) + A subtile 0, one cp.async group ----
    {
        const float4* gBh = (const float4*)(g_Bhi + (size_t)nt * TILE_E);
        const float4* gBl = (const float4*)(g_Blo + (size_t)nt * TILE_E);
        for (int i = tid; i < 3200; i += 256) {
            CP16(sb + OFF_BHI + i * 16, gBh + i);
            CP16(sb + OFF_BLO + i * 16, gBl + i);
        }
    }
    {
        const int st = mg * 8;   // first 64-row subtile index
        const float4* gAh = (const float4*)(g_Ahi + (size_t)(st >> 1) * TILE_E)
                            + (st & 1) * 1600;
        const float4* gAl = (const float4*)(g_Alo + (size_t)(st >> 1) * TILE_E)
                            + (st & 1) * 1600;
        for (int i = tid; i < 1600; i += 256) {
            CP16(sb + OFF_A + i * 16, gAh + i);
            CP16(sb + OFF_A + 25600 + i * 16, gAl + i);
        }
    }
    asm volatile("cp.async.commit_group;" ::: "memory");

    const int wm = wid & 1;        // m-half (32 rows)
    const int wn = wid >> 1;       // n-quarter (32 cols)

    const uint32_t abyte = (uint32_t)((wm * 32 + (l & 15)) * 400 + ((l >> 4) & 1) * 16);
    const uint32_t bbyte = (uint32_t)((wn * 32 + (l & 7) + ((l >> 4) & 1) * 8) * 400
                                      + ((l >> 3) & 1) * 16);

    // bias (per-CTA constant across subtiles)
    float fb0[4], fb1[4];
#pragma unroll
    for (int ni = 0; ni < 4; ++ni) {
        int n = n0 + wn * 32 + ni * 8 + (l & 3) * 2;
        fb0[ni] = (n < N_OUT)     ? __ldg(fc_b + n)     : 0.f;
        fb1[ni] = (n + 1 < N_OUT) ? __ldg(fc_b + n + 1) : 0.f;
    }
    const int nvalid = N_OUT - n0;

    asm volatile("cp.async.wait_group 0;" ::: "memory");
    __syncthreads();

    for (int i2 = 0; i2 < 8; ++i2) {
        // prefetch next A subtile into the other buffer
        if (i2 < 7) {
            const int st = mg * 8 + i2 + 1;
            const uint32_t dst = sb + OFF_A + ((i2 + 1) & 1) * 51200;
            const float4* gAh = (const float4*)(g_Ahi + (size_t)(st >> 1) * TILE_E)
                                + (st & 1) * 1600;
            const float4* gAl = (const float4*)(g_Alo + (size_t)(st >> 1) * TILE_E)
                                + (st & 1) * 1600;
            for (int i = tid; i < 1600; i += 256) {
                CP16(dst + i * 16, gAh + i);
                CP16(dst + 25600 + i * 16, gAl + i);
            }
            asm volatile("cp.async.commit_group;" ::: "memory");
        }

        // ---- compute subtile i2 from buf[i2&1] ----
        const uint32_t Abase = sb + OFF_A + (i2 & 1) * 51200;

        float acc[2][4][4];
#pragma unroll
        for (int mi = 0; mi < 2; ++mi)
#pragma unroll
            for (int ni = 0; ni < 4; ++ni)
#pragma unroll
                for (int r = 0; r < 4; ++r) acc[mi][ni][r] = 0.f;

#pragma unroll
        for (int t3 = 0; t3 < 3; ++t3) {
            const uint32_t Ab = Abase + (t3 == 2 ? 25600u : 0u) + abyte;
            const uint32_t Bb = sb + (t3 == 1 ? OFF_BLO : OFF_BHI) + bbyte;
#pragma unroll 4
            for (int ks = 0; ks < 12; ++ks) {
                const uint32_t ko = ks * 32;
                uint32_t a[2][4];
                LDSM4(a[0], Ab + ko);
                LDSM4(a[1], Ab + 6400 + ko);
                uint32_t bq0[4], bq1[4];
                LDSM4(bq0, Bb + ko);
                LDSM4(bq1, Bb + 6400 + ko);
#pragma unroll
                for (int mi = 0; mi < 2; ++mi) {
                    MMA16816(acc[mi][0], a[mi], bq0[0], bq0[1]);
                    MMA16816(acc[mi][1], a[mi], bq0[2], bq0[3]);
                    MMA16816(acc[mi][2], a[mi], bq1[0], bq1[1]);
                    MMA16816(acc[mi][3], a[mi], bq1[2], bq1[3]);
                }
            }
        }

        // ---- epilogue (overlaps the prefetch) ----
        const int mbase = (mg * 8 + i2) * 64 + wm * 32 + (l >> 2);
#pragma unroll
        for (int ni = 0; ni < 4; ++ni) {
            const int n = wn * 32 + ni * 8 + (l & 3) * 2;
            if (n < nvalid) {
#pragma unroll
                for (int mi = 0; mi < 2; ++mi) {
                    const int m = mbase + mi * 16;
                    float* p0 = out + (size_t)m * N_OUT + n0 + n;
                    float* p1 = out + (size_t)(m + 8) * N_OUT + n0 + n;
                    *(float2*)p0 = make_float2(acc[mi][ni][0] + fb0[ni],
                                               acc[mi][ni][1] + fb1[ni]);
                    *(float2*)p1 = make_float2(acc[mi][ni][2] + fb0[ni],
                                               acc[mi][ni][3] + fb1[ni]);
                }
            }
        }

        if (i2 < 7) {
            asm volatile("cp.async.wait_group 0;" ::: "memory");
            __syncthreads();
        }
    }
}

// ---------------------------------------------------------------------------
extern "C" void kernel_launch(void* const* d_in, const int* in_sizes, int n_in,
                              void* d_out, int out_size) {
    const float* x          = (const float*)d_in[0];
    const float* conv_w     = (const float*)d_in[1];
    const float* bn_gamma   = (const float*)d_in[2];
    const float* bn_beta    = (const float*)d_in[3];
    const float* bn_mean    = (const float*)d_in[4];
    const float* bn_var     = (const float*)d_in[5];
    const float* in_proj_w  = (const float*)d_in[6];
    const float* in_proj_b  = (const float*)d_in[7];
    const float* out_proj_w = (const float*)d_in[8];
    const float* out_proj_b = (const float*)d_in[9];
    const float* fc_w       = (const float*)d_in[10];
    const float* fc_b       = (const float*)d_in[11];
    float* out = (float*)d_out;

    cudaFuncSetAttribute(fc_mma_kernel,
                         cudaFuncAttributeMaxDynamicSharedMemorySize, SMEM_TOTAL);

    prep_b_kernel<<<(N_OUT * K_DIM + 255) / 256, 256>>>(fc_w);
    head_kernel<<<B_BATCH, 768>>>(x, conv_w, bn_gamma, bn_beta, bn_mean, bn_var,
                                  in_proj_w, in_proj_b, out_proj_w, out_proj_b);
    fc_mma_kernel<<<dim3(NT, 8), 256, SMEM_TOTAL>>>(fc_b, out);
}